// round 6
// baseline (speedup 1.0000x reference)
#include <cuda_runtime.h>
#include <cuda_bf16.h>
#include <math.h>
#include <stdint.h>

#define H        4096
#define E        64
#define TM       128              // tokens per block
#define KC       64               // k per chunk
#define NC       (H / KC)         // 64
#define NTHREADS 256

// dynamic smem (bytes): X limbs [buf][limb] 128x128B, then W limbs [buf][limb] 64x128B
#define XB(buf, limb) (((buf) << 15) + ((limb) << 14))
#define WOFF 65536
#define WB(buf, limb) (WOFF + ((buf) << 14) + ((limb) << 13))
#define SMEM_BYTES 98304

// W limbs (scale folded), [limb][expert*512 + k/8], 16B-aligned for cp.async
__device__ uint4 g_wl[2][E * (H / 8)];

static __device__ __forceinline__ void split2(float x, float y, uint32_t& hi, uint32_t& lo) {
    asm("cvt.rn.bf16x2.f32 %0, %1, %2;" : "=r"(hi) : "f"(y), "f"(x));   // low16 = bf16(x)
    const float hx = __uint_as_float(hi << 16);
    const float hy = __uint_as_float(hi & 0xFFFF0000u);
    const float rx = x - hx, ry = y - hy;
    asm("cvt.rn.bf16x2.f32 %0, %1, %2;" : "=r"(lo) : "f"(ry), "f"(rx));
}

__global__ void wprep_kernel(const float* __restrict__ wg, const float* __restrict__ sg)
{
    const int e = blockIdx.x;
    const int t = threadIdx.x;
    #pragma unroll
    for (int i = 0; i < 2; i++) {
        const int u = t + 256 * i;          // uint4 index within row (0..511) = 8 floats
        const float4 wA = ((const float4*)(wg + (size_t)e * H))[u * 2];
        const float4 wB = ((const float4*)(wg + (size_t)e * H))[u * 2 + 1];
        const float4 sA = ((const float4*)sg)[u * 2];
        const float4 sB = ((const float4*)sg)[u * 2 + 1];
        float4 a = wA, b = wB;
        a.x *= sA.x; a.y *= sA.y; a.z *= sA.z; a.w *= sA.w;
        b.x *= sB.x; b.y *= sB.y; b.z *= sB.z; b.w *= sB.w;
        uint32_t h0, l0, h1, l1, h2, l2, h3, l3;
        split2(a.x, a.y, h0, l0);  split2(a.z, a.w, h1, l1);
        split2(b.x, b.y, h2, l2);  split2(b.z, b.w, h3, l3);
        g_wl[0][e * 512 + u] = make_uint4(h0, h1, h2, h3);
        g_wl[1][e * 512 + u] = make_uint4(l0, l1, l2, l3);
    }
}

#define LDSM4(r0, r1, r2, r3, addr) \
    asm volatile("ldmatrix.sync.aligned.m8n8.x4.shared.b16 {%0,%1,%2,%3}, [%4];" \
                 : "=r"(r0), "=r"(r1), "=r"(r2), "=r"(r3) : "r"(addr))

#define MMA(acc, a, b0, b1) \
    asm volatile("mma.sync.aligned.m16n8k16.row.col.f32.bf16.bf16.f32 " \
                 "{%0,%1,%2,%3},{%4,%5,%6,%7},{%8,%9},{%0,%1,%2,%3};" \
                 : "+f"((acc)[0]), "+f"((acc)[1]), "+f"((acc)[2]), "+f"((acc)[3]) \
                 : "r"((a)[0]), "r"((a)[1]), "r"((a)[2]), "r"((a)[3]), "r"(b0), "r"(b1))

#define STS128(addr, v0, v1, v2, v3) \
    asm volatile("st.shared.v4.b32 [%0], {%1,%2,%3,%4};" \
                 :: "r"(addr), "r"(v0), "r"(v1), "r"(v2), "r"(v3))

#define CPASYNC16(dst, src) \
    asm volatile("cp.async.ca.shared.global [%0], [%1], 16;" :: "r"(dst), "l"(src))

// out layout (fp32): probs[ntok][64] | top_k_weights[ntok][2] | top_k_index[ntok][2]

__global__ __launch_bounds__(NTHREADS, 1)
void router_kernel(const float* __restrict__ xg, const float* __restrict__ pes,
                   float* __restrict__ out, int ntok)
{
    extern __shared__ char smem[];
    __shared__ float ssq[TM];
    __shared__ float topw[TM * 2];
    __shared__ float topi[TM * 2];

    uint32_t sb;
    asm("{ .reg .u64 t; cvta.to.shared.u64 t, %1; cvt.u32.u64 %0, t; }" : "=r"(sb) : "l"(smem));

    const int tid  = threadIdx.x;
    const int tok0 = blockIdx.x * TM;
    if (tid < TM) ssq[tid] = 0.f;

    // ---- X load/convert: row r (0..127), half = which 32-float half of the chunk row
    const int r    = tid >> 1;
    const int half = tid & 1;
    const float* xrow = xg + (size_t)(tok0 + r) * H + half * 32;
    float ssql = 0.f;

    // ---- W cp.async: limb wl, expert row wr, 4 x 16B each
    const int wl  = tid >> 7;
    const int wr  = (tid >> 1) & 63;
    const int wc0 = (tid & 1) * 4;
    const char* wsrc_base = (const char*)&g_wl[wl][wr * 512];
    const uint32_t wxor = (uint32_t)(wr & 7);

    // ---- warp tile: m32 x n32 per warp; 4 m-groups x 2 n-groups
    const int lane = tid & 31;
    const int wid  = tid >> 5;
    const int m0 = (wid >> 1) << 5;            // 0,32,64,96
    const int n0 = (wid & 1) << 5;             // 0,32
    const int arow0 = m0 + (lane & 15);
    const int arow1 = arow0 + 16;
    const int apar  = lane >> 4;
    const int axor  = arow0 & 7;               // same for arow1 (+16)
    const int brow0 = n0 + (lane & 7) + ((lane >> 4) << 3);
    const int brow1 = brow0 + 16;
    const int bpar  = (lane >> 3) & 1;

    float acc[2][4][4];
    #pragma unroll
    for (int mt = 0; mt < 2; mt++)
        #pragma unroll
        for (int nt = 0; nt < 4; nt++)
            #pragma unroll
            for (int j = 0; j < 4; j++) acc[mt][nt][j] = 0.f;

    // ---- prologue: W chunk0 cp.async, X chunk0 LDG
    {
        const uint32_t wdst = sb + WB(0, wl) + (uint32_t)wr * 128;
        #pragma unroll
        for (int j = 0; j < 4; j++) {
            const uint32_t cc = (uint32_t)(wc0 + j);
            CPASYNC16(wdst + ((cc ^ wxor) << 4), wsrc_base + cc * 16);
        }
        asm volatile("cp.async.commit_group;" ::: "memory");
    }
    float4 xa[8];
    #pragma unroll
    for (int u = 0; u < 4; u++) {
        xa[2 * u]     = *(const float4*)(xrow + u * 8);
        xa[2 * u + 1] = *(const float4*)(xrow + u * 8 + 4);
    }

    for (int c = 0; c < NC; c++) {
        const int buf = c & 1;

        // ---- sumsq + split + STS X chunk c
        {
            const uint32_t rb = sb + XB(buf, 0) + (uint32_t)r * 128;
            #pragma unroll
            for (int u = 0; u < 4; u++) {
                const float4 a = xa[2 * u], b = xa[2 * u + 1];
                ssql += a.x*a.x + a.y*a.y + a.z*a.z + a.w*a.w
                      + b.x*b.x + b.y*b.y + b.z*b.z + b.w*b.w;
                uint32_t h0,l0,h1,l1,h2,l2,h3,l3;
                split2(a.x, a.y, h0, l0);  split2(a.z, a.w, h1, l1);
                split2(b.x, b.y, h2, l2);  split2(b.z, b.w, h3, l3);
                const uint32_t d = rb + (uint32_t)(((half * 4 + u) ^ (r & 7)) << 4);
                STS128(d,         h0, h1, h2, h3);
                STS128(d + 16384, l0, l1, l2, l3);
            }
        }

        // ---- prefetch X chunk c+1
        if (c + 1 < NC) {
            const size_t k2 = (size_t)(c + 1) * KC;
            #pragma unroll
            for (int u = 0; u < 4; u++) {
                xa[2 * u]     = *(const float4*)(xrow + k2 + u * 8);
                xa[2 * u + 1] = *(const float4*)(xrow + k2 + u * 8 + 4);
            }
        }

        asm volatile("cp.async.wait_group 0;" ::: "memory");
        __syncthreads();

        // ---- issue W chunk c+1 into buf^1
        if (c + 1 < NC) {
            const uint32_t wdst = sb + WB(buf ^ 1, wl) + (uint32_t)wr * 128;
            const char* ws = wsrc_base + (size_t)(c + 1) * 128;
            #pragma unroll
            for (int j = 0; j < 4; j++) {
                const uint32_t cc = (uint32_t)(wc0 + j);
                CPASYNC16(wdst + ((cc ^ wxor) << 4), ws + cc * 16);
            }
            asm volatile("cp.async.commit_group;" ::: "memory");
        }

        // ---- mma chunk c: 4 k-steps x (8 ldmatrix.x4 + 24 HMMA)
        #pragma unroll
        for (int ks = 0; ks < 4; ks++) {
            uint32_t A[2][2][4], B[2][8];       // [limb][mt], [limb]
            #pragma unroll
            for (int l = 0; l < 2; l++) {
                const uint32_t xbase = sb + XB(buf, l);
                const uint32_t wbase = sb + WB(buf, l);
                const uint32_t ao = (uint32_t)((((ks << 1) + apar) ^ axor) << 4);
                LDSM4(A[l][0][0], A[l][0][1], A[l][0][2], A[l][0][3],
                      xbase + (uint32_t)arow0 * 128 + ao);
                LDSM4(A[l][1][0], A[l][1][1], A[l][1][2], A[l][1][3],
                      xbase + (uint32_t)arow1 * 128 + ao);
                const uint32_t b0a = wbase + (uint32_t)brow0 * 128
                                   + (uint32_t)((((ks << 1) + bpar) ^ (brow0 & 7)) << 4);
                const uint32_t b1a = wbase + (uint32_t)brow1 * 128
                                   + (uint32_t)((((ks << 1) + bpar) ^ (brow1 & 7)) << 4);
                LDSM4(B[l][0], B[l][1], B[l][2], B[l][3], b0a);
                LDSM4(B[l][4], B[l][5], B[l][6], B[l][7], b1a);
            }
            #pragma unroll
            for (int mt = 0; mt < 2; mt++)
                #pragma unroll
                for (int nt = 0; nt < 4; nt++) {
                    MMA(acc[mt][nt], A[0][mt], B[0][nt * 2], B[0][nt * 2 + 1]);  // hi*hi
                    MMA(acc[mt][nt], A[0][mt], B[1][nt * 2], B[1][nt * 2 + 1]);  // hi*lo
                    MMA(acc[mt][nt], A[1][mt], B[0][nt * 2], B[0][nt * 2 + 1]);  // lo*hi
                }
        }
    }

    atomicAdd(&ssq[r], ssql);
    __syncthreads();

    // ---- dump accumulators to padded score tile sc[128][68]
    float* sc = (float*)smem;
    {
        const int colb = n0 + (lane & 3) * 2;
        #pragma unroll
        for (int mt = 0; mt < 2; mt++) {
            const int row0 = m0 + 16 * mt + (lane >> 2);
            #pragma unroll
            for (int nt = 0; nt < 4; nt++) {
                const int col = colb + nt * 8;
                sc[row0 * 68 + col]           = acc[mt][nt][0];
                sc[row0 * 68 + col + 1]       = acc[mt][nt][1];
                sc[(row0 + 8) * 68 + col]     = acc[mt][nt][2];
                sc[(row0 + 8) * 68 + col + 1] = acc[mt][nt][3];
            }
        }
    }
    __syncthreads();

    // ---- per-token RMSNorm factor + softmax + top-2
    if (tid < TM) {
        const int t = tid;
        const float rr = 1.0f / (64.0f * sqrtf(ssq[t] * (1.0f / 4096.0f) + 1e-6f));
        float m = -1e30f;
        #pragma unroll 8
        for (int e = 0; e < E; e++) m = fmaxf(m, sc[t * 68 + e] * rr);
        float sum = 0.f, m1 = -1.f, m2 = -1.f;
        int i1 = 0, i2 = 0;
        for (int e = 0; e < E; e++) {
            const float ex = __expf(sc[t * 68 + e] * rr - m);
            sum += ex;
            sc[t * 68 + e] = ex;
            if (ex > m1)      { m2 = m1; i2 = i1; m1 = ex; i1 = e; }
            else if (ex > m2) { m2 = ex; i2 = e; }
        }
        const float inv = 1.0f / sum;
        #pragma unroll 8
        for (int e = 0; e < E; e++) sc[t * 68 + e] *= inv;
        const float dn = 1.0f / (m1 + m2);
        topw[t * 2 + 0] = m1 * dn * pes[i1];
        topw[t * 2 + 1] = m2 * dn * pes[i2];
        topi[t * 2 + 0] = (float)i1;
        topi[t * 2 + 1] = (float)i2;
    }
    __syncthreads();

    // ---- outputs (2048 float4 of probs; sc rows are 16B-aligned: 68*4 = 272 = 17*16)
    float4* pout = (float4*)(out + (size_t)tok0 * 64);
    #pragma unroll
    for (int q = 0; q < 8; q++) {
        const int idx = tid + 256 * q;
        const int row = idx >> 4;
        const int c4  = idx & 15;
        pout[idx] = *(const float4*)&sc[row * 68 + c4 * 4];
    }
    float* wout = out + (size_t)ntok * 64;
    float* iout = wout + (size_t)ntok * 2;
    wout[tok0 * 2 + tid] = topw[tid];
    iout[tok0 * 2 + tid] = topi[tid];
}

extern "C" void kernel_launch(void* const* d_in, const int* in_sizes, int n_in,
                              void* d_out, int out_size)
{
    (void)n_in; (void)out_size;
    const float* x   = (const float*)d_in[0];
    const float* w   = (const float*)d_in[1];
    const float* s   = (const float*)d_in[2];
    const float* pes = (const float*)d_in[3];
    const int ntok = in_sizes[0] / H;            // 16384
    wprep_kernel<<<E, 256>>>(w, s);
    cudaFuncSetAttribute(router_kernel, cudaFuncAttributeMaxDynamicSharedMemorySize, SMEM_BYTES);
    router_kernel<<<ntok / TM, NTHREADS, SMEM_BYTES>>>(x, pes, (float*)d_out, ntok);
}

// round 9
// speedup vs baseline: 1.2659x; 1.2659x over previous
#include <cuda_runtime.h>
#include <cuda_bf16.h>
#include <math.h>
#include <stdint.h>

#define H        4096
#define E        64
#define TM       64               // tokens per block
#define KC       64               // k per chunk
#define NC       (H / KC)         // 64
#define NTHREADS 256

// dynamic smem (bytes): X limbs [buf][limb] 64x128B, then W limbs [buf][limb] 64x128B
#define XB(buf, limb) (((buf) << 14) + ((limb) << 13))
#define WOFF 32768
#define WB(buf, limb) (WOFF + ((buf) << 14) + ((limb) << 13))
#define SMEM_BYTES 65536

// W limbs (scale folded), [limb][expert*512 + k/8], 16B-aligned for cp.async
__device__ uint4 g_wl[2][E * (H / 8)];

static __device__ __forceinline__ void split2(float x, float y, uint32_t& hi, uint32_t& lo) {
    asm("cvt.rn.bf16x2.f32 %0, %1, %2;" : "=r"(hi) : "f"(y), "f"(x));   // low16 = bf16(x)
    const float hx = __uint_as_float(hi << 16);
    const float hy = __uint_as_float(hi & 0xFFFF0000u);
    const float rx = x - hx, ry = y - hy;
    asm("cvt.rn.bf16x2.f32 %0, %1, %2;" : "=r"(lo) : "f"(ry), "f"(rx));
}

__global__ void wprep_kernel(const float* __restrict__ wg, const float* __restrict__ sg)
{
    const int e = blockIdx.x;
    const int t = threadIdx.x;
    #pragma unroll
    for (int i = 0; i < 2; i++) {
        const int u = t + 256 * i;          // uint4 index within row (0..511) = 8 floats
        const float4 wA = ((const float4*)(wg + (size_t)e * H))[u * 2];
        const float4 wB = ((const float4*)(wg + (size_t)e * H))[u * 2 + 1];
        const float4 sA = ((const float4*)sg)[u * 2];
        const float4 sB = ((const float4*)sg)[u * 2 + 1];
        float4 a = wA, b = wB;
        a.x *= sA.x; a.y *= sA.y; a.z *= sA.z; a.w *= sA.w;
        b.x *= sB.x; b.y *= sB.y; b.z *= sB.z; b.w *= sB.w;
        uint32_t h0, l0, h1, l1, h2, l2, h3, l3;
        split2(a.x, a.y, h0, l0);  split2(a.z, a.w, h1, l1);
        split2(b.x, b.y, h2, l2);  split2(b.z, b.w, h3, l3);
        g_wl[0][e * 512 + u] = make_uint4(h0, h1, h2, h3);
        g_wl[1][e * 512 + u] = make_uint4(l0, l1, l2, l3);
    }
}

#define LDSM4(r0, r1, r2, r3, addr) \
    asm volatile("ldmatrix.sync.aligned.m8n8.x4.shared.b16 {%0,%1,%2,%3}, [%4];" \
                 : "=r"(r0), "=r"(r1), "=r"(r2), "=r"(r3) : "r"(addr))

#define MMA(acc, a, b0, b1) \
    asm volatile("mma.sync.aligned.m16n8k16.row.col.f32.bf16.bf16.f32 " \
                 "{%0,%1,%2,%3},{%4,%5,%6,%7},{%8,%9},{%0,%1,%2,%3};" \
                 : "+f"((acc)[0]), "+f"((acc)[1]), "+f"((acc)[2]), "+f"((acc)[3]) \
                 : "r"((a)[0]), "r"((a)[1]), "r"((a)[2]), "r"((a)[3]), "r"(b0), "r"(b1))

#define STS128(addr, v0, v1, v2, v3) \
    asm volatile("st.shared.v4.b32 [%0], {%1,%2,%3,%4};" \
                 :: "r"(addr), "r"(v0), "r"(v1), "r"(v2), "r"(v3))

#define CPASYNC16(dst, src) \
    asm volatile("cp.async.ca.shared.global [%0], [%1], 16;" :: "r"(dst), "l"(src))

// out layout (fp32): probs[ntok][64] | top_k_weights[ntok][2] | top_k_index[ntok][2]

__global__ __launch_bounds__(NTHREADS, 2)
void router_kernel(const float* __restrict__ xg, const float* __restrict__ pes,
                   float* __restrict__ out, int ntok)
{
    extern __shared__ char smem[];
    __shared__ float ssq[TM];
    __shared__ float topw[TM * 2];
    __shared__ float topi[TM * 2];

    uint32_t sb;
    asm("{ .reg .u64 t; cvta.to.shared.u64 t, %1; cvt.u32.u64 %0, t; }" : "=r"(sb) : "l"(smem));

    const int tid  = threadIdx.x;
    const int tok0 = blockIdx.x * TM;
    if (tid < TM) ssq[tid] = 0.f;

    // ---- X load/convert assignment: row r (0..63), p = quarter pattern
    const int r = tid >> 2;
    const int p = tid & 3;
    const float* xrow = xg + (size_t)(tok0 + r) * H + 8 * p;
    float ssql = 0.f;

    // ---- W cp.async: limb wl, expert row wr, 4 x 16B each
    const int wl  = tid >> 7;
    const int wr  = (tid >> 1) & 63;
    const int wc0 = (tid & 1) * 4;
    const char* wsrc_base = (const char*)&g_wl[wl][wr * 512];
    const uint32_t wxor = (uint32_t)(wr & 7);

    // ---- warp roles: 4 m-tiles x 2 K-groups; each warp m16 x n64
    const int lane = tid & 31;
    const int wid  = tid >> 5;
    const int kg   = wid >> 2;                 // K-group: chunks with (c&1)==kg
    const int m0   = (wid & 3) << 4;           // 0,16,32,48
    const int arow = m0 + (lane & 15);
    const int apar = lane >> 4;
    const int axor = arow & 7;
    const int brow_in = (lane & 7) + ((lane >> 4) << 3);   // 0..15 within n16 group
    const int bpar    = (lane >> 3) & 1;

    float acc[8][4];                           // 8 n8-tiles x 4 regs (m16 x n64)
    #pragma unroll
    for (int nt = 0; nt < 8; nt++)
        #pragma unroll
        for (int j = 0; j < 4; j++) acc[nt][j] = 0.f;

    // ---- prologue: W chunk0 cp.async, X chunk0 LDG
    {
        const uint32_t wdst = sb + WB(0, wl) + (uint32_t)wr * 128;
        #pragma unroll
        for (int j = 0; j < 4; j++) {
            const uint32_t cc = (uint32_t)(wc0 + j);
            CPASYNC16(wdst + ((cc ^ wxor) << 4), wsrc_base + cc * 16);
        }
        asm volatile("cp.async.commit_group;" ::: "memory");
    }
    float4 x0 = *(const float4*)(xrow);
    float4 x1 = *(const float4*)(xrow + 4);
    float4 x2 = *(const float4*)(xrow + 32);
    float4 x3 = *(const float4*)(xrow + 36);

    for (int c = 0; c < NC; c++) {
        const int buf = c & 1;

        // ---- sumsq + split + STS X chunk c
        ssql += x0.x*x0.x + x0.y*x0.y + x0.z*x0.z + x0.w*x0.w
              + x1.x*x1.x + x1.y*x1.y + x1.z*x1.z + x1.w*x1.w
              + x2.x*x2.x + x2.y*x2.y + x2.z*x2.z + x2.w*x2.w
              + x3.x*x3.x + x3.y*x3.y + x3.z*x3.z + x3.w*x3.w;
        {
            uint32_t h0,l0,h1,l1,h2,l2,h3,l3,h4,l4,h5,l5,h6,l6,h7,l7;
            split2(x0.x, x0.y, h0, l0);  split2(x0.z, x0.w, h1, l1);
            split2(x1.x, x1.y, h2, l2);  split2(x1.z, x1.w, h3, l3);
            split2(x2.x, x2.y, h4, l4);  split2(x2.z, x2.w, h5, l5);
            split2(x3.x, x3.y, h6, l6);  split2(x3.z, x3.w, h7, l7);
            const uint32_t rb = sb + XB(buf, 0) + (uint32_t)r * 128;
            const uint32_t d0 = rb + (uint32_t)((p       ^ (r & 7)) << 4);
            const uint32_t d1 = rb + (uint32_t)(((p + 4) ^ (r & 7)) << 4);
            STS128(d0,        h0, h1, h2, h3);
            STS128(d0 + 8192, l0, l1, l2, l3);
            STS128(d1,        h4, h5, h6, h7);
            STS128(d1 + 8192, l4, l5, l6, l7);
        }

        // ---- prefetch X chunk c+1
        if (c + 1 < NC) {
            const size_t k2 = (size_t)(c + 1) * KC;
            x0 = *(const float4*)(xrow + k2);
            x1 = *(const float4*)(xrow + k2 + 4);
            x2 = *(const float4*)(xrow + k2 + 32);
            x3 = *(const float4*)(xrow + k2 + 36);
        }

        asm volatile("cp.async.wait_group 0;" ::: "memory");
        __syncthreads();

        // ---- issue W chunk c+1 into buf^1
        if (c + 1 < NC) {
            const uint32_t wdst = sb + WB(buf ^ 1, wl) + (uint32_t)wr * 128;
            const char* ws = wsrc_base + (size_t)(c + 1) * 128;
            #pragma unroll
            for (int j = 0; j < 4; j++) {
                const uint32_t cc = (uint32_t)(wc0 + j);
                CPASYNC16(wdst + ((cc ^ wxor) << 4), ws + cc * 16);
            }
            asm volatile("cp.async.commit_group;" ::: "memory");
        }

        // ---- mma chunk c: only this chunk's K-group; 4 ks x (10 LDSM.x4 + 24 HMMA)
        if (kg == buf) {
            #pragma unroll
            for (int ks = 0; ks < 4; ks++) {
                uint32_t A[2][4];
                const uint32_t ao = (uint32_t)((((ks << 1) + apar) ^ axor) << 4);
                LDSM4(A[0][0], A[0][1], A[0][2], A[0][3],
                      sb + XB(buf, 0) + (uint32_t)arow * 128 + ao);
                LDSM4(A[1][0], A[1][1], A[1][2], A[1][3],
                      sb + XB(buf, 1) + (uint32_t)arow * 128 + ao);
                #pragma unroll
                for (int ng = 0; ng < 4; ng++) {        // n16 groups
                    const int brow = ng * 16 + brow_in;
                    const uint32_t bo = (uint32_t)((((ks << 1) + bpar) ^ (brow & 7)) << 4)
                                      + (uint32_t)brow * 128;
                    uint32_t B0[4], B1[4];
                    LDSM4(B0[0], B0[1], B0[2], B0[3], sb + WB(buf, 0) + bo);
                    LDSM4(B1[0], B1[1], B1[2], B1[3], sb + WB(buf, 1) + bo);
                    MMA(acc[ng * 2],     A[0], B0[0], B0[1]);   // hi*hi
                    MMA(acc[ng * 2],     A[0], B1[0], B1[1]);   // hi*lo
                    MMA(acc[ng * 2],     A[1], B0[0], B0[1]);   // lo*hi
                    MMA(acc[ng * 2 + 1], A[0], B0[2], B0[3]);
                    MMA(acc[ng * 2 + 1], A[0], B1[2], B1[3]);
                    MMA(acc[ng * 2 + 1], A[1], B0[2], B0[3]);
                }
            }
        }
    }

    atomicAdd(&ssq[r], ssql);
    __syncthreads();

    // ---- K-group reduction into padded score tile sc[64][68]
    float* sc = (float*)smem;
    {
        const int row0 = m0 + (lane >> 2);
        const int colb = (lane & 3) * 2;
        if (kg == 0) {
            #pragma unroll
            for (int nt = 0; nt < 8; nt++) {
                const int col = colb + nt * 8;
                sc[row0 * 68 + col]           = acc[nt][0];
                sc[row0 * 68 + col + 1]       = acc[nt][1];
                sc[(row0 + 8) * 68 + col]     = acc[nt][2];
                sc[(row0 + 8) * 68 + col + 1] = acc[nt][3];
            }
        }
        __syncthreads();
        if (kg == 1) {
            #pragma unroll
            for (int nt = 0; nt < 8; nt++) {
                const int col = colb + nt * 8;
                sc[row0 * 68 + col]           += acc[nt][0];
                sc[row0 * 68 + col + 1]       += acc[nt][1];
                sc[(row0 + 8) * 68 + col]     += acc[nt][2];
                sc[(row0 + 8) * 68 + col + 1] += acc[nt][3];
            }
        }
    }
    __syncthreads();

    // ---- per-token RMSNorm factor + softmax + top-2
    if (tid < TM) {
        const int t = tid;
        const float rr = 1.0f / (64.0f * sqrtf(ssq[t] * (1.0f / 4096.0f) + 1e-6f));
        float m = -1e30f;
        #pragma unroll 8
        for (int e = 0; e < E; e++) m = fmaxf(m, sc[t * 68 + e] * rr);
        float sum = 0.f, m1 = -1.f, m2 = -1.f;
        int i1 = 0, i2 = 0;
        for (int e = 0; e < E; e++) {
            const float ex = __expf(sc[t * 68 + e] * rr - m);
            sum += ex;
            sc[t * 68 + e] = ex;
            if (ex > m1)      { m2 = m1; i2 = i1; m1 = ex; i1 = e; }
            else if (ex > m2) { m2 = ex; i2 = e; }
        }
        const float inv = 1.0f / sum;
        #pragma unroll 8
        for (int e = 0; e < E; e++) sc[t * 68 + e] *= inv;
        const float dn = 1.0f / (m1 + m2);
        topw[t * 2 + 0] = m1 * dn * pes[i1];
        topw[t * 2 + 1] = m2 * dn * pes[i2];
        topi[t * 2 + 0] = (float)i1;
        topi[t * 2 + 1] = (float)i2;
    }
    __syncthreads();

    // ---- outputs (1024 float4 of probs)
    float4* pout = (float4*)(out + (size_t)tok0 * 64);
    #pragma unroll
    for (int q = 0; q < 4; q++) {
        const int idx = tid + 256 * q;
        const int row = idx >> 4;
        const int c4  = idx & 15;
        pout[idx] = *(const float4*)&sc[row * 68 + c4 * 4];
    }
    float* wout = out + (size_t)ntok * 64;
    float* iout = wout + (size_t)ntok * 2;
    if (tid < TM * 2) {
        wout[tok0 * 2 + tid] = topw[tid];
        iout[tok0 * 2 + tid] = topi[tid];
    }
}

extern "C" void kernel_launch(void* const* d_in, const int* in_sizes, int n_in,
                              void* d_out, int out_size)
{
    (void)n_in; (void)out_size;
    const float* x   = (const float*)d_in[0];
    const float* w   = (const float*)d_in[1];
    const float* s   = (const float*)d_in[2];
    const float* pes = (const float*)d_in[3];
    const int ntok = in_sizes[0] / H;            // 16384
    wprep_kernel<<<E, 256>>>(w, s);
    cudaFuncSetAttribute(router_kernel, cudaFuncAttributeMaxDynamicSharedMemorySize, SMEM_BYTES);
    router_kernel<<<ntok / TM, NTHREADS, SMEM_BYTES>>>(x, pes, (float*)d_out, ntok);
}

// round 11
// speedup vs baseline: 1.6501x; 1.3034x over previous
#include <cuda_runtime.h>
#include <cuda_bf16.h>
#include <math.h>
#include <stdint.h>

#define H        4096
#define E        64
#define TM       128              // tokens per block
#define KC       64               // k per chunk
#define NC       (H / KC)         // 64
#define NTHREADS 512

// dynamic smem (bytes): X limbs [buf][limb] 128x128B, then W limbs [buf][limb] 64x128B
#define XB(buf, limb) (((buf) << 15) + ((limb) << 14))
#define WOFF 65536
#define WB(buf, limb) (WOFF + ((buf) << 14) + ((limb) << 13))
#define SMEM_BYTES 98304

// W limbs (scale folded), [limb][expert*512 + k/8], 16B-aligned for cp.async
__device__ uint4 g_wl[2][E * (H / 8)];

static __device__ __forceinline__ void split2(float x, float y, uint32_t& hi, uint32_t& lo) {
    asm("cvt.rn.bf16x2.f32 %0, %1, %2;" : "=r"(hi) : "f"(y), "f"(x));   // low16 = bf16(x)
    const float hx = __uint_as_float(hi << 16);
    const float hy = __uint_as_float(hi & 0xFFFF0000u);
    const float rx = x - hx, ry = y - hy;
    asm("cvt.rn.bf16x2.f32 %0, %1, %2;" : "=r"(lo) : "f"(ry), "f"(rx));
}

__global__ void wprep_kernel(const float* __restrict__ wg, const float* __restrict__ sg)
{
    const int e = blockIdx.x;
    const int t = threadIdx.x;
    #pragma unroll
    for (int i = 0; i < 2; i++) {
        const int u = t + 256 * i;          // uint4 index within row (0..511) = 8 floats
        const float4 wA = ((const float4*)(wg + (size_t)e * H))[u * 2];
        const float4 wB = ((const float4*)(wg + (size_t)e * H))[u * 2 + 1];
        const float4 sA = ((const float4*)sg)[u * 2];
        const float4 sB = ((const float4*)sg)[u * 2 + 1];
        float4 a = wA, b = wB;
        a.x *= sA.x; a.y *= sA.y; a.z *= sA.z; a.w *= sA.w;
        b.x *= sB.x; b.y *= sB.y; b.z *= sB.z; b.w *= sB.w;
        uint32_t h0, l0, h1, l1, h2, l2, h3, l3;
        split2(a.x, a.y, h0, l0);  split2(a.z, a.w, h1, l1);
        split2(b.x, b.y, h2, l2);  split2(b.z, b.w, h3, l3);
        g_wl[0][e * 512 + u] = make_uint4(h0, h1, h2, h3);
        g_wl[1][e * 512 + u] = make_uint4(l0, l1, l2, l3);
    }
}

#define LDSM4(r0, r1, r2, r3, addr) \
    asm volatile("ldmatrix.sync.aligned.m8n8.x4.shared.b16 {%0,%1,%2,%3}, [%4];" \
                 : "=r"(r0), "=r"(r1), "=r"(r2), "=r"(r3) : "r"(addr))

#define MMA(acc, a, b0, b1) \
    asm volatile("mma.sync.aligned.m16n8k16.row.col.f32.bf16.bf16.f32 " \
                 "{%0,%1,%2,%3},{%4,%5,%6,%7},{%8,%9},{%0,%1,%2,%3};" \
                 : "+f"((acc)[0]), "+f"((acc)[1]), "+f"((acc)[2]), "+f"((acc)[3]) \
                 : "r"((a)[0]), "r"((a)[1]), "r"((a)[2]), "r"((a)[3]), "r"(b0), "r"(b1))

#define STS128(addr, v0, v1, v2, v3) \
    asm volatile("st.shared.v4.b32 [%0], {%1,%2,%3,%4};" \
                 :: "r"(addr), "r"(v0), "r"(v1), "r"(v2), "r"(v3))

#define CPASYNC16(dst, src) \
    asm volatile("cp.async.ca.shared.global [%0], [%1], 16;" :: "r"(dst), "l"(src))

// out layout (fp32): probs[ntok][64] | top_k_weights[ntok][2] | top_k_index[ntok][2]

__global__ __launch_bounds__(NTHREADS, 1)
void router_kernel(const float* __restrict__ xg, const float* __restrict__ pes,
                   float* __restrict__ out, int ntok)
{
    extern __shared__ char smem[];
    __shared__ float ssq[TM];
    __shared__ float topw[TM * 2];
    __shared__ float topi[TM * 2];

    uint32_t sb;
    asm("{ .reg .u64 t; cvta.to.shared.u64 t, %1; cvt.u32.u64 %0, t; }" : "=r"(sb) : "l"(smem));

    const int tid  = threadIdx.x;
    const int tok0 = blockIdx.x * TM;
    if (tid < TM) ssq[tid] = 0.f;

    // ---- X load/convert assignment: row r (0..127), p = quarter pattern
    const int r = tid >> 2;
    const int p = tid & 3;
    const float* xrow = xg + (size_t)(tok0 + r) * H + 8 * p;
    float ssql = 0.f;

    // ---- W cp.async: limb wl, expert row wr, 2 consecutive 16B pieces
    const int wl  = tid >> 8;
    const int wr  = (tid >> 2) & 63;
    const int wc0 = (tid & 3) * 2;
    const char* wsrc_base = (const char*)&g_wl[wl][wr * 512];
    const uint32_t wxor = (uint32_t)(wr & 7);

    // ---- warp roles: 2 K-groups x 4 m-tiles(m32) x 2 n-tiles(n32)
    const int lane = tid & 31;
    const int wid  = tid >> 5;                 // 0..15
    const int kg   = wid >> 3;                 // chunks with (c&1)==kg
    const int mi   = (wid >> 1) & 3;
    const int ni   = wid & 1;
    const int m0   = mi << 5;                  // 0,32,64,96
    const int n0   = ni << 5;                  // 0,32
    const int arow0 = m0 + (lane & 15);
    const int arow1 = arow0 + 16;
    const int apar  = lane >> 4;
    const int axor  = arow0 & 7;               // same for arow1
    const int brow_in = (lane & 7) + ((lane >> 4) << 3);
    const int bpar    = (lane >> 3) & 1;

    float acc[2][4][4];                        // [mt][nt(4 n8 of n32)][4]
    #pragma unroll
    for (int mt = 0; mt < 2; mt++)
        #pragma unroll
        for (int nt = 0; nt < 4; nt++)
            #pragma unroll
            for (int j = 0; j < 4; j++) acc[mt][nt][j] = 0.f;

    // ---- prologue: W chunk0 cp.async, X chunk0 LDG
    {
        const uint32_t wdst = sb + WB(0, wl) + (uint32_t)wr * 128;
        #pragma unroll
        for (int j = 0; j < 2; j++) {
            const uint32_t cc = (uint32_t)(wc0 + j);
            CPASYNC16(wdst + ((cc ^ wxor) << 4), wsrc_base + cc * 16);
        }
        asm volatile("cp.async.commit_group;" ::: "memory");
    }
    float4 x0 = *(const float4*)(xrow);
    float4 x1 = *(const float4*)(xrow + 4);
    float4 x2 = *(const float4*)(xrow + 32);
    float4 x3 = *(const float4*)(xrow + 36);

    for (int c = 0; c < NC; c++) {
        const int buf = c & 1;

        // ---- sumsq + split + STS X chunk c
        ssql += x0.x*x0.x + x0.y*x0.y + x0.z*x0.z + x0.w*x0.w
              + x1.x*x1.x + x1.y*x1.y + x1.z*x1.z + x1.w*x1.w
              + x2.x*x2.x + x2.y*x2.y + x2.z*x2.z + x2.w*x2.w
              + x3.x*x3.x + x3.y*x3.y + x3.z*x3.z + x3.w*x3.w;
        {
            uint32_t h0,l0,h1,l1,h2,l2,h3,l3,h4,l4,h5,l5,h6,l6,h7,l7;
            split2(x0.x, x0.y, h0, l0);  split2(x0.z, x0.w, h1, l1);
            split2(x1.x, x1.y, h2, l2);  split2(x1.z, x1.w, h3, l3);
            split2(x2.x, x2.y, h4, l4);  split2(x2.z, x2.w, h5, l5);
            split2(x3.x, x3.y, h6, l6);  split2(x3.z, x3.w, h7, l7);
            const uint32_t rb = sb + XB(buf, 0) + (uint32_t)r * 128;
            const uint32_t d0 = rb + (uint32_t)((p       ^ (r & 7)) << 4);
            const uint32_t d1 = rb + (uint32_t)(((p + 4) ^ (r & 7)) << 4);
            STS128(d0,         h0, h1, h2, h3);
            STS128(d0 + 16384, l0, l1, l2, l3);
            STS128(d1,         h4, h5, h6, h7);
            STS128(d1 + 16384, l4, l5, l6, l7);
        }

        // ---- prefetch X chunk c+1
        if (c + 1 < NC) {
            const size_t k2 = (size_t)(c + 1) * KC;
            x0 = *(const float4*)(xrow + k2);
            x1 = *(const float4*)(xrow + k2 + 4);
            x2 = *(const float4*)(xrow + k2 + 32);
            x3 = *(const float4*)(xrow + k2 + 36);
        }

        asm volatile("cp.async.wait_group 0;" ::: "memory");
        __syncthreads();

        // ---- issue W chunk c+1 into buf^1
        if (c + 1 < NC) {
            const uint32_t wdst = sb + WB(buf ^ 1, wl) + (uint32_t)wr * 128;
            const char* ws = wsrc_base + (size_t)(c + 1) * 128;
            #pragma unroll
            for (int j = 0; j < 2; j++) {
                const uint32_t cc = (uint32_t)(wc0 + j);
                CPASYNC16(wdst + ((cc ^ wxor) << 4), ws + cc * 16);
            }
            asm volatile("cp.async.commit_group;" ::: "memory");
        }

        // ---- mma chunk c: only this chunk's K-group; 4 ks x (8 LDSM.x4 + 24 HMMA)
        if (kg == buf) {
            #pragma unroll
            for (int ks = 0; ks < 4; ks++) {
                uint32_t A[2][2][4];               // [limb][mt]
                const uint32_t ao = (uint32_t)((((ks << 1) + apar) ^ axor) << 4);
                #pragma unroll
                for (int l = 0; l < 2; l++) {
                    const uint32_t xb = sb + XB(buf, l);
                    LDSM4(A[l][0][0], A[l][0][1], A[l][0][2], A[l][0][3],
                          xb + (uint32_t)arow0 * 128 + ao);
                    LDSM4(A[l][1][0], A[l][1][1], A[l][1][2], A[l][1][3],
                          xb + (uint32_t)arow1 * 128 + ao);
                }
                #pragma unroll
                for (int ng = 0; ng < 2; ng++) {   // n16 groups within n32
                    const int brow = n0 + ng * 16 + brow_in;
                    const uint32_t bo = (uint32_t)((((ks << 1) + bpar) ^ (brow & 7)) << 4)
                                      + (uint32_t)brow * 128;
                    uint32_t B0[4], B1[4];
                    LDSM4(B0[0], B0[1], B0[2], B0[3], sb + WB(buf, 0) + bo);
                    LDSM4(B1[0], B1[1], B1[2], B1[3], sb + WB(buf, 1) + bo);
                    #pragma unroll
                    for (int mt = 0; mt < 2; mt++) {
                        MMA(acc[mt][ng * 2],     A[0][mt], B0[0], B0[1]);   // hi*hi
                        MMA(acc[mt][ng * 2],     A[0][mt], B1[0], B1[1]);   // hi*lo
                        MMA(acc[mt][ng * 2],     A[1][mt], B0[0], B0[1]);   // lo*hi
                        MMA(acc[mt][ng * 2 + 1], A[0][mt], B0[2], B0[3]);
                        MMA(acc[mt][ng * 2 + 1], A[0][mt], B1[2], B1[3]);
                        MMA(acc[mt][ng * 2 + 1], A[1][mt], B0[2], B0[3]);
                    }
                }
            }
        }
    }

    atomicAdd(&ssq[r], ssql);
    __syncthreads();

    // ---- K-group reduction into padded score tile sc[128][68]
    float* sc = (float*)smem;
    {
        const int colb = n0 + (lane & 3) * 2;
        if (kg == 0) {
            #pragma unroll
            for (int mt = 0; mt < 2; mt++) {
                const int row0 = m0 + mt * 16 + (lane >> 2);
                #pragma unroll
                for (int nt = 0; nt < 4; nt++) {
                    const int col = colb + nt * 8;
                    sc[row0 * 68 + col]           = acc[mt][nt][0];
                    sc[row0 * 68 + col + 1]       = acc[mt][nt][1];
                    sc[(row0 + 8) * 68 + col]     = acc[mt][nt][2];
                    sc[(row0 + 8) * 68 + col + 1] = acc[mt][nt][3];
                }
            }
        }
        __syncthreads();
        if (kg == 1) {
            #pragma unroll
            for (int mt = 0; mt < 2; mt++) {
                const int row0 = m0 + mt * 16 + (lane >> 2);
                #pragma unroll
                for (int nt = 0; nt < 4; nt++) {
                    const int col = colb + nt * 8;
                    sc[row0 * 68 + col]           += acc[mt][nt][0];
                    sc[row0 * 68 + col + 1]       += acc[mt][nt][1];
                    sc[(row0 + 8) * 68 + col]     += acc[mt][nt][2];
                    sc[(row0 + 8) * 68 + col + 1] += acc[mt][nt][3];
                }
            }
        }
    }
    __syncthreads();

    // ---- per-token RMSNorm factor + softmax + top-2
    if (tid < TM) {
        const int t = tid;
        const float rr = 1.0f / (64.0f * sqrtf(ssq[t] * (1.0f / 4096.0f) + 1e-6f));
        float m = -1e30f;
        #pragma unroll 8
        for (int e = 0; e < E; e++) m = fmaxf(m, sc[t * 68 + e] * rr);
        float sum = 0.f, m1 = -1.f, m2 = -1.f;
        int i1 = 0, i2 = 0;
        for (int e = 0; e < E; e++) {
            const float ex = __expf(sc[t * 68 + e] * rr - m);
            sum += ex;
            sc[t * 68 + e] = ex;
            if (ex > m1)      { m2 = m1; i2 = i1; m1 = ex; i1 = e; }
            else if (ex > m2) { m2 = ex; i2 = e; }
        }
        const float inv = 1.0f / sum;
        #pragma unroll 8
        for (int e = 0; e < E; e++) sc[t * 68 + e] *= inv;
        const float dn = 1.0f / (m1 + m2);
        topw[t * 2 + 0] = m1 * dn * pes[i1];
        topw[t * 2 + 1] = m2 * dn * pes[i2];
        topi[t * 2 + 0] = (float)i1;
        topi[t * 2 + 1] = (float)i2;
    }
    __syncthreads();

    // ---- outputs (2048 float4 of probs)
    float4* pout = (float4*)(out + (size_t)tok0 * 64);
    #pragma unroll
    for (int q = 0; q < 4; q++) {
        const int idx = tid + NTHREADS * q;
        const int row = idx >> 4;
        const int c4  = idx & 15;
        pout[idx] = *(const float4*)&sc[row * 68 + c4 * 4];
    }
    float* wout = out + (size_t)ntok * 64;
    float* iout = wout + (size_t)ntok * 2;
    if (tid < TM * 2) {
        wout[tok0 * 2 + tid] = topw[tid];
        iout[tok0 * 2 + tid] = topi[tid];
    }
}

extern "C" void kernel_launch(void* const* d_in, const int* in_sizes, int n_in,
                              void* d_out, int out_size)
{
    (void)n_in; (void)out_size;
    const float* x   = (const float*)d_in[0];
    const float* w   = (const float*)d_in[1];
    const float* s   = (const float*)d_in[2];
    const float* pes = (const float*)d_in[3];
    const int ntok = in_sizes[0] / H;            // 16384
    wprep_kernel<<<E, 256>>>(w, s);
    cudaFuncSetAttribute(router_kernel, cudaFuncAttributeMaxDynamicSharedMemorySize, SMEM_BYTES);
    router_kernel<<<ntok / TM, NTHREADS, SMEM_BYTES>>>(x, pes, (float*)d_out, ntok);
}